// round 6
// baseline (speedup 1.0000x reference)
#include <cuda_runtime.h>
#include <cuda_fp16.h>
#include <cfloat>
#include <cstdint>

#define BB 8
#define NN 16384
#define SS 2048
#define DD 64

__device__ float g_pnorm[BB * NN];
__device__ int   g_topk[BB * SS * 32];
__device__ float g_h2[BB * NN * 128];
__device__ float g_w0f[64 * 64], g_w1f[64 * 64], g_w2f[128 * 64];
__device__ float g_b0f[64], g_b1f[64], g_b2f[128];

// ---------------- warp-MMA helpers (sm_80+ ISA; no 'a'-suffix features) ----
__device__ __forceinline__ uint32_t smem_u32(const void* p) {
    uint32_t a;
    asm("{ .reg .u64 t; cvta.to.shared.u64 t, %1; cvt.u32.u64 %0, t; }" : "=r"(a) : "l"(p));
    return a;
}
__device__ __forceinline__ void ldsm_x2(uint32_t& r0, uint32_t& r1, uint32_t a) {
    asm volatile("ldmatrix.sync.aligned.m8n8.x2.shared.b16 {%0,%1}, [%2];"
                 : "=r"(r0), "=r"(r1) : "r"(a));
}
__device__ __forceinline__ void ldsm_x4(uint32_t* r, uint32_t a) {
    asm volatile("ldmatrix.sync.aligned.m8n8.x4.shared.b16 {%0,%1,%2,%3}, [%4];"
                 : "=r"(r[0]), "=r"(r[1]), "=r"(r[2]), "=r"(r[3]) : "r"(a));
}
__device__ __forceinline__ void mma_f16(float* c, const uint32_t* a, uint32_t b0, uint32_t b1) {
    asm volatile(
        "mma.sync.aligned.m16n8k16.row.col.f32.f16.f16.f32 "
        "{%0,%1,%2,%3}, {%4,%5,%6,%7}, {%8,%9}, {%0,%1,%2,%3};"
        : "+f"(c[0]), "+f"(c[1]), "+f"(c[2]), "+f"(c[3])
        : "r"(a[0]), "r"(a[1]), "r"(a[2]), "r"(a[3]), "r"(b0), "r"(b1));
}
// pack (x, y) floats as two fp16 (rn) into one u32: lo halfword = x
__device__ __forceinline__ uint32_t pack_h2(float x, float y) {
    __half2 h = __floats2half2_rn(x, y);
    return *(uint32_t*)&h;
}
__device__ __forceinline__ float h_hi(float x) {          // value of fp16_rn(x)
    return __half2float(__float2half_rn(x));
}

#define DOT4STEP(wv, h0, h1, h2v, h3, A, Bc) \
    A  = fmaf((h0), (wv).x, A);  Bc = fmaf((h1), (wv).y, Bc); \
    A  = fmaf((h2v), (wv).z, A); Bc = fmaf((h3), (wv).w, Bc);

// ---------------- weight/BN folding ----------------
__global__ void k_prep(const float* __restrict__ w0, const float* __restrict__ b0,
                       const float* __restrict__ gg0, const float* __restrict__ be0,
                       const float* __restrict__ m0, const float* __restrict__ v0,
                       const float* __restrict__ w1, const float* __restrict__ b1,
                       const float* __restrict__ gg1, const float* __restrict__ be1,
                       const float* __restrict__ m1, const float* __restrict__ v1,
                       const float* __restrict__ w2, const float* __restrict__ b2,
                       const float* __restrict__ gg2, const float* __restrict__ be2,
                       const float* __restrict__ m2, const float* __restrict__ v2) {
    int o = threadIdx.x;
    if (o < 64) {
        float s0 = gg0[o] * rsqrtf(v0[o] + 1e-5f);
        for (int c = 0; c < 64; c++) g_w0f[o * 64 + c] = w0[o * 64 + c] * s0;
        g_b0f[o] = (b0[o] - m0[o]) * s0 + be0[o];
        float s1 = gg1[o] * rsqrtf(v1[o] + 1e-5f);
        for (int c = 0; c < 64; c++) g_w1f[o * 64 + c] = w1[o * 64 + c] * s1;
        g_b1f[o] = (b1[o] - m1[o]) * s1 + be1[o];
    }
    float s2 = gg2[o] * rsqrtf(v2[o] + 1e-5f);
    for (int c = 0; c < 64; c++) g_w2f[o * 64 + c] = w2[o * 64 + c] * s2;
    g_b2f[o] = (b2[o] - m2[o]) * s2 + be2[o];
}

__global__ void k_pnorm(const float* __restrict__ points) {
    int i = blockIdx.x * blockDim.x + threadIdx.x;
    const float4* p = (const float4*)(points + (size_t)i * DD);
    float a0 = 0, a1 = 0, a2 = 0, a3 = 0;
#pragma unroll
    for (int u = 0; u < 16; u++) {
        float4 v = p[u];
        a0 = fmaf(v.x, v.x, a0); a1 = fmaf(v.y, v.y, a1);
        a2 = fmaf(v.z, v.z, a2); a3 = fmaf(v.w, v.w, a3);
    }
    g_pnorm[i] = (a0 + a1) + (a2 + a3);
}

__global__ void k_newxyz(const float* __restrict__ xyz, const int* __restrict__ sidx,
                         float* __restrict__ out) {
    int t = blockIdx.x * blockDim.x + threadIdx.x;
    if (t >= BB * SS * 3) return;
    int c = t % 3, s = (t / 3) % SS, b = t / (3 * SS);
    out[t] = xyz[((size_t)b * NN + sidx[s]) * 3 + c];
}

// ---------------- pointwise 3-layer MLP (unchanged) ----------------
__global__ void __launch_bounds__(128, 1) k_mlp(const float* __restrict__ points) {
    __shared__ float sh0[64 * 128];
    const int tid = threadIdx.x;
    const size_t pt = (size_t)blockIdx.x * 128 + tid;
    float4 x[16];
    {
        const float4* xp = (const float4*)(points + pt * DD);
#pragma unroll
        for (int u = 0; u < 16; u++) x[u] = xp[u];
    }
    for (int o4 = 0; o4 < 16; o4++) {
        const float4* wr0 = (const float4*)(g_w0f + (o4 * 4 + 0) * 64);
        const float4* wr1 = (const float4*)(g_w0f + (o4 * 4 + 1) * 64);
        const float4* wr2 = (const float4*)(g_w0f + (o4 * 4 + 2) * 64);
        const float4* wr3 = (const float4*)(g_w0f + (o4 * 4 + 3) * 64);
        float A0 = 0, A1 = 0, A2 = 0, A3 = 0, C0 = 0, C1 = 0, C2 = 0, C3 = 0;
#pragma unroll
        for (int u = 0; u < 16; u++) {
            float h0 = x[u].x, h1 = x[u].y, h2v = x[u].z, h3 = x[u].w;
            float4 w0v = wr0[u]; DOT4STEP(w0v, h0, h1, h2v, h3, A0, C0);
            float4 w1v = wr1[u]; DOT4STEP(w1v, h0, h1, h2v, h3, A1, C1);
            float4 w2v = wr2[u]; DOT4STEP(w2v, h0, h1, h2v, h3, A2, C2);
            float4 w3v = wr3[u]; DOT4STEP(w3v, h0, h1, h2v, h3, A3, C3);
        }
        sh0[(o4 * 4 + 0) * 128 + tid] = fmaxf(A0 + C0 + g_b0f[o4 * 4 + 0], 0.f);
        sh0[(o4 * 4 + 1) * 128 + tid] = fmaxf(A1 + C1 + g_b0f[o4 * 4 + 1], 0.f);
        sh0[(o4 * 4 + 2) * 128 + tid] = fmaxf(A2 + C2 + g_b0f[o4 * 4 + 2], 0.f);
        sh0[(o4 * 4 + 3) * 128 + tid] = fmaxf(A3 + C3 + g_b0f[o4 * 4 + 3], 0.f);
    }
    float h1r[64];
#pragma unroll
    for (int o4 = 0; o4 < 16; o4++) {
        const float4* wr0 = (const float4*)(g_w1f + (o4 * 4 + 0) * 64);
        const float4* wr1 = (const float4*)(g_w1f + (o4 * 4 + 1) * 64);
        const float4* wr2 = (const float4*)(g_w1f + (o4 * 4 + 2) * 64);
        const float4* wr3 = (const float4*)(g_w1f + (o4 * 4 + 3) * 64);
        float A0 = 0, A1 = 0, A2 = 0, A3 = 0, C0 = 0, C1 = 0, C2 = 0, C3 = 0;
#pragma unroll
        for (int u = 0; u < 16; u++) {
            float h0 = sh0[(4 * u + 0) * 128 + tid];
            float h1 = sh0[(4 * u + 1) * 128 + tid];
            float h2v = sh0[(4 * u + 2) * 128 + tid];
            float h3 = sh0[(4 * u + 3) * 128 + tid];
            float4 w0v = wr0[u]; DOT4STEP(w0v, h0, h1, h2v, h3, A0, C0);
            float4 w1v = wr1[u]; DOT4STEP(w1v, h0, h1, h2v, h3, A1, C1);
            float4 w2v = wr2[u]; DOT4STEP(w2v, h0, h1, h2v, h3, A2, C2);
            float4 w3v = wr3[u]; DOT4STEP(w3v, h0, h1, h2v, h3, A3, C3);
        }
        h1r[o4 * 4 + 0] = fmaxf(A0 + C0 + g_b1f[o4 * 4 + 0], 0.f);
        h1r[o4 * 4 + 1] = fmaxf(A1 + C1 + g_b1f[o4 * 4 + 1], 0.f);
        h1r[o4 * 4 + 2] = fmaxf(A2 + C2 + g_b1f[o4 * 4 + 2], 0.f);
        h1r[o4 * 4 + 3] = fmaxf(A3 + C3 + g_b1f[o4 * 4 + 3], 0.f);
    }
    float* stg = sh0;
    const size_t obase = (size_t)blockIdx.x * 128 * 128;
    for (int ch = 0; ch < 4; ch++) {
        __syncthreads();
        for (int o4 = 0; o4 < 8; o4++) {
            const int ob = ch * 32 + o4 * 4;
            const float4* wr0 = (const float4*)(g_w2f + (ob + 0) * 64);
            const float4* wr1 = (const float4*)(g_w2f + (ob + 1) * 64);
            const float4* wr2 = (const float4*)(g_w2f + (ob + 2) * 64);
            const float4* wr3 = (const float4*)(g_w2f + (ob + 3) * 64);
            float A0 = 0, A1 = 0, A2 = 0, A3 = 0, C0 = 0, C1 = 0, C2 = 0, C3 = 0;
#pragma unroll
            for (int u = 0; u < 16; u++) {
                float h0 = h1r[4 * u + 0], h1 = h1r[4 * u + 1];
                float h2v = h1r[4 * u + 2], h3 = h1r[4 * u + 3];
                float4 w0v = wr0[u]; DOT4STEP(w0v, h0, h1, h2v, h3, A0, C0);
                float4 w1v = wr1[u]; DOT4STEP(w1v, h0, h1, h2v, h3, A1, C1);
                float4 w2v = wr2[u]; DOT4STEP(w2v, h0, h1, h2v, h3, A2, C2);
                float4 w3v = wr3[u]; DOT4STEP(w3v, h0, h1, h2v, h3, A3, C3);
            }
            stg[(o4 * 4 + 0) * 129 + tid] = fmaxf(A0 + C0 + g_b2f[ob + 0], 0.f);
            stg[(o4 * 4 + 1) * 129 + tid] = fmaxf(A1 + C1 + g_b2f[ob + 1], 0.f);
            stg[(o4 * 4 + 2) * 129 + tid] = fmaxf(A2 + C2 + g_b2f[ob + 2], 0.f);
            stg[(o4 * 4 + 3) * 129 + tid] = fmaxf(A3 + C3 + g_b2f[ob + 3], 0.f);
        }
        __syncthreads();
        const int lane = tid & 31, grp = tid >> 5;
#pragma unroll 4
        for (int rr = grp; rr < 128; rr += 4) {
            g_h2[obase + (size_t)rr * 128 + ch * 32 + lane] = stg[lane * 129 + rr];
        }
    }
}

// ============================================================================
// k_dist_mma: fp16 mma.sync 4-pass-split distance GEMM + fused pnorm + top-32
// ============================================================================
// smem byte offsets
#define O_BHI  0u            // [2][128][64] fp16 (16KB each)
#define O_BLO  32768u
#define O_PN   65536u        // [2][128][16] fp16 (4KB each); elems 0,1 = hi,lo
#define O_LV   73728u        // list values  [128][32] f32
#define O_LI   90112u        // list indices [128][32] i32
#define O_THR  106496u       // [128] f32
#define O_SCR  107008u       // [8 warps][8][128] f32
#define DSMEM  139776

// swizzled byte offset inside a [128 rows x 128B] tile
__device__ __forceinline__ uint32_t bswz(int row, int kbyte) {
    return (uint32_t)(row * 128 + (kbyte ^ ((row & 7) << 4)));
}

// insert candidate into row list (evict lexicographic max (val, idx)); returns new thr
__device__ __noinline__ float row_insert(float* lv, int* li, float sc, int idx) {
    float m = lv[0]; int mi = li[0]; int ms = 0;
#pragma unroll
    for (int j = 1; j < 32; j++) {
        float v = lv[j];
        if (v > m || (v == m && li[j] > mi)) { m = v; mi = li[j]; ms = j; }
    }
    lv[ms] = sc; li[ms] = idx;
    m = lv[0];
#pragma unroll
    for (int j = 1; j < 32; j++) m = fmaxf(m, lv[j]);
    return m;
}

__global__ void __launch_bounds__(256, 1) k_dist_mma(const float* __restrict__ points,
                                                     const int* __restrict__ sidx) {
    extern __shared__ char sm[];
    const uint32_t sb = smem_u32(sm);
    const int tid = threadIdx.x, lane = tid & 31, w = tid >> 5;
    const int b = blockIdx.y, s0 = blockIdx.x * 128;

    float* listv = (float*)(sm + O_LV);
    int*   listi = (int*)(sm + O_LI);
    float* sthr  = (float*)(sm + O_THR);
    float* scr   = (float*)(sm + O_SCR) + w * 8 * 128;

    // init lists / thresholds / pn padding zeros
    for (int j = tid; j < 128 * 32; j += 256) { listv[j] = FLT_MAX; listi[j] = 0; }
    if (tid < 128) sthr[tid] = FLT_MAX;
    for (int j = tid; j < 2048; j += 256) ((uint32_t*)(sm + O_PN))[j] = 0;

    // ---- stage A = -2*q, split hi/lo into BHI[0]/BLO[0], then ldmatrix frags ----
    {
        const int row = tid >> 1, kh = (tid & 1) * 32;
        const int qi = __ldg(sidx + s0 + row);
        const float4* qp = (const float4*)(points + ((size_t)b * NN + qi) * DD + kh);
#pragma unroll
        for (int u = 0; u < 8; u++) {
            float4 v = qp[u];
            float f0 = -2.f * v.x, f1 = -2.f * v.y, f2 = -2.f * v.z, f3 = -2.f * v.w;
            float h0 = h_hi(f0), h1 = h_hi(f1), h2 = h_hi(f2), h3 = h_hi(f3);
            int k = kh + u * 4;
            uint32_t off = bswz(row, 2 * k);
            *(uint2*)(sm + O_BHI + off) =
                make_uint2(pack_h2(h0, h1), pack_h2(h2, h3));
            *(uint2*)(sm + O_BLO + off) =
                make_uint2(pack_h2(f0 - h0, f1 - h1), pack_h2(f2 - h2, f3 - h3));
        }
    }
    __syncthreads();

    uint32_t Ah[4][4], Al[4][4], Apn[4];
    {
        const int m = lane >> 3;
        const int arow = 16 * w + (lane & 7) + ((m & 1) << 3);
#pragma unroll
        for (int c = 0; c < 4; c++) {
            int kb = c * 32 + ((m >> 1) << 4);
            uint32_t off = bswz(arow, kb);
            ldsm_x4(Ah[c], sb + O_BHI + off);
            ldsm_x4(Al[c], sb + O_BLO + off);
        }
        uint32_t one2 = ((lane & 3) == 0) ? 0x3C003C00u : 0u;  // fp16 {1,1} at cols 0,1
        Apn[0] = one2; Apn[1] = one2; Apn[2] = 0; Apn[3] = 0;
    }
    __syncthreads();

    // ---- load tile 0 into buffer 0 ----
    const int prow = tid >> 1, pkh = (tid & 1) * 32;
    const float* Pbase = points + (size_t)b * NN * DD;
    {
        const float4* src = (const float4*)(Pbase + (size_t)prow * DD + pkh);
#pragma unroll
        for (int u = 0; u < 8; u++) {
            float4 v = src[u];
            float h0 = h_hi(v.x), h1 = h_hi(v.y), h2 = h_hi(v.z), h3 = h_hi(v.w);
            int k = pkh + u * 4;
            uint32_t off = bswz(prow, 2 * k);
            *(uint2*)(sm + O_BHI + off) = make_uint2(pack_h2(h0, h1), pack_h2(h2, h3));
            *(uint2*)(sm + O_BLO + off) =
                make_uint2(pack_h2(v.x - h0, v.y - h1), pack_h2(v.z - h2, v.w - h3));
        }
        if (tid < 128) {
            float pn = g_pnorm[b * NN + tid];
            float ph = h_hi(pn);
            *(uint32_t*)(sm + O_PN + tid * 32) = pack_h2(ph, pn - ph);
        }
    }
    __syncthreads();

    // lane-invariant address pieces for B ldmatrix
    const int li16 = lane & 15;
    const uint32_t browterm = (uint32_t)((li16 & 7) * 128);
    const uint32_t bswzl = (uint32_t)((li16 & 7) << 4);
    const uint32_t bhalf16 = (uint32_t)((li16 >> 3) << 4);      // +16B for 2nd matrix
    const uint32_t pnlane = sb + O_PN + (uint32_t)((li16 & 7) * 32) + bhalf16;

    // ---- main loop over 128 point tiles ----
    for (int t = 0; t < 128; t++) {
        const int cur = t & 1, nxt = cur ^ 1;

        // prefetch next tile into registers
        float4 pf[8]; float pfn = 0.f;
        if (t < 127) {
            const float4* src =
                (const float4*)(Pbase + (size_t)(t + 1) * 128 * DD + (size_t)prow * DD + pkh);
#pragma unroll
            for (int u = 0; u < 8; u++) pf[u] = src[u];
            if (tid < 128) pfn = g_pnorm[b * NN + (t + 1) * 128 + tid];
        }

        // ---- compute: 16 n-frags x (9 LDSM + 17 MMA, full 4-pass split) ----
        float acc[64];
#pragma unroll
        for (int j = 0; j < 64; j++) acc[j] = 0.f;
        const uint32_t bhib = sb + O_BHI + cur * 16384u + browterm;
        const uint32_t blob = sb + O_BLO + cur * 16384u + browterm;
        const uint32_t pnb = pnlane + cur * 4096u;
#pragma unroll
        for (int nf = 0; nf < 16; nf++) {
            uint32_t bh[4][2], bl[4][2], bp0, bp1;
#pragma unroll
            for (int c = 0; c < 4; c++) {
                uint32_t kb = ((uint32_t)(c * 32) + bhalf16) ^ bswzl;
                ldsm_x2(bh[c][0], bh[c][1], bhib + nf * 1024u + kb);
                ldsm_x2(bl[c][0], bl[c][1], blob + nf * 1024u + kb);
            }
            ldsm_x2(bp0, bp1, pnb + nf * 256u);
            float* C = acc + nf * 4;
#pragma unroll
            for (int c = 0; c < 4; c++) mma_f16(C, Ah[c], bh[c][0], bh[c][1]);
#pragma unroll
            for (int c = 0; c < 4; c++) mma_f16(C, Ah[c], bl[c][0], bl[c][1]);
#pragma unroll
            for (int c = 0; c < 4; c++) mma_f16(C, Al[c], bh[c][0], bh[c][1]);
#pragma unroll
            for (int c = 0; c < 4; c++) mma_f16(C, Al[c], bl[c][0], bl[c][1]);
            mma_f16(C, Apn, bp0, bp1);
        }

        // ---- fast row-min gate ----
        float mn0 = FLT_MAX, mn1 = FLT_MAX;
#pragma unroll
        for (int nf = 0; nf < 16; nf++) {
            mn0 = fminf(mn0, fminf(acc[nf * 4 + 0], acc[nf * 4 + 1]));
            mn1 = fminf(mn1, fminf(acc[nf * 4 + 2], acc[nf * 4 + 3]));
        }
        mn0 = fminf(mn0, __shfl_xor_sync(0xffffffffu, mn0, 1));
        mn0 = fminf(mn0, __shfl_xor_sync(0xffffffffu, mn0, 2));
        mn1 = fminf(mn1, __shfl_xor_sync(0xffffffffu, mn1, 1));
        mn1 = fminf(mn1, __shfl_xor_sync(0xffffffffu, mn1, 2));
        const int g = lane >> 2;
        const int r0 = 16 * w + g, r1 = r0 + 8;
        bool f0 = mn0 < sthr[r0];
        bool f1 = mn1 < sthr[r1];

        if (__ballot_sync(0xffffffffu, f0 || f1)) {
            // half 0 (rows 16w+g)
            if (f0) {
#pragma unroll
                for (int nf = 0; nf < 16; nf++)
                    *(float2*)&scr[g * 128 + nf * 8 + 2 * (lane & 3)] =
                        make_float2(acc[nf * 4 + 0], acc[nf * 4 + 1]);
            }
            __syncwarp();
            if (f0 && (lane & 3) == 0) {
                float thr = sthr[r0];
                float* lv = listv + r0 * 32; int* lix = listi + r0 * 32;
                const float* srow = scr + g * 128;
                for (int c = 0; c < 128; c += 4) {
                    float4 v = *(const float4*)(srow + c);
                    if (v.x < thr) thr = row_insert(lv, lix, v.x, t * 128 + c);
                    if (v.y < thr) thr = row_insert(lv, lix, v.y, t * 128 + c + 1);
                    if (v.z < thr) thr = row_insert(lv, lix, v.z, t * 128 + c + 2);
                    if (v.w < thr) thr = row_insert(lv, lix, v.w, t * 128 + c + 3);
                }
                sthr[r0] = thr;
            }
            __syncwarp();
            // half 1 (rows 16w+8+g)
            if (f1) {
#pragma unroll
                for (int nf = 0; nf < 16; nf++)
                    *(float2*)&scr[g * 128 + nf * 8 + 2 * (lane & 3)] =
                        make_float2(acc[nf * 4 + 2], acc[nf * 4 + 3]);
            }
            __syncwarp();
            if (f1 && (lane & 3) == 0) {
                float thr = sthr[r1];
                float* lv = listv + r1 * 32; int* lix = listi + r1 * 32;
                const float* srow = scr + g * 128;
                for (int c = 0; c < 128; c += 4) {
                    float4 v = *(const float4*)(srow + c);
                    if (v.x < thr) thr = row_insert(lv, lix, v.x, t * 128 + c);
                    if (v.y < thr) thr = row_insert(lv, lix, v.y, t * 128 + c + 1);
                    if (v.z < thr) thr = row_insert(lv, lix, v.z, t * 128 + c + 2);
                    if (v.w < thr) thr = row_insert(lv, lix, v.w, t * 128 + c + 3);
                }
                sthr[r1] = thr;
            }
            __syncwarp();
        }

        __syncthreads();   // all warps done reading buf[cur] & writing before refill

        // ---- store prefetched tile into buf[nxt] ----
        if (t < 127) {
#pragma unroll
            for (int u = 0; u < 8; u++) {
                float4 v = pf[u];
                float h0 = h_hi(v.x), h1 = h_hi(v.y), h2 = h_hi(v.z), h3 = h_hi(v.w);
                int k = pkh + u * 4;
                uint32_t off = bswz(prow, 2 * k) + nxt * 16384u;
                *(uint2*)(sm + O_BHI + off) = make_uint2(pack_h2(h0, h1), pack_h2(h2, h3));
                *(uint2*)(sm + O_BLO + off) =
                    make_uint2(pack_h2(v.x - h0, v.y - h1), pack_h2(v.z - h2, v.w - h3));
            }
            if (tid < 128) {
                float ph = h_hi(pfn);
                *(uint32_t*)(sm + O_PN + nxt * 4096u + tid * 32) = pack_h2(ph, pfn - ph);
            }
            __syncthreads();
        }
    }

    __syncthreads();
    // write out top-32 index lists
    for (int j = tid; j < 128 * 32; j += 256) {
        int r = j >> 5;
        g_topk[((size_t)b * SS + s0 + r) * 32 + (j & 31)] = listi[j];
    }
}

// ---------------- gather + channel max over the 32 neighbors ----------------
__global__ void k_gmax(float* __restrict__ out) {
    const int b = blockIdx.y, s = blockIdx.x, c = threadIdx.x;
    __shared__ int si[32];
    if (threadIdx.x < 32) si[threadIdx.x] = g_topk[((size_t)b * SS + s) * 32 + threadIdx.x];
    __syncthreads();
    const float* hb = g_h2 + (size_t)b * NN * 128;
    float m = -FLT_MAX;
#pragma unroll 8
    for (int j = 0; j < 32; j++) m = fmaxf(m, hb[(size_t)si[j] * 128 + c]);
    out[((size_t)b * SS + s) * 128 + c] = m;
}

// ---------------- launch ----------------
extern "C" void kernel_launch(void* const* d_in, const int* in_sizes, int n_in,
                              void* d_out, int out_size) {
    const float* xyz    = (const float*)d_in[0];
    const float* points = (const float*)d_in[1];
    const int*   sidx   = (const int*)d_in[2];

    float* out = (float*)d_out;
    float* out_xyz = nullptr;
    float* out_pts = out;
    if (out_size == BB * SS * 3 + BB * SS * 128) {
        out_xyz = out;
        out_pts = out + BB * SS * 3;
    }

    cudaFuncSetAttribute(k_dist_mma, cudaFuncAttributeMaxDynamicSharedMemorySize, DSMEM);

    k_prep<<<1, 128>>>((const float*)d_in[3], (const float*)d_in[4], (const float*)d_in[5],
                       (const float*)d_in[6], (const float*)d_in[7], (const float*)d_in[8],
                       (const float*)d_in[9], (const float*)d_in[10], (const float*)d_in[11],
                       (const float*)d_in[12], (const float*)d_in[13], (const float*)d_in[14],
                       (const float*)d_in[15], (const float*)d_in[16], (const float*)d_in[17],
                       (const float*)d_in[18], (const float*)d_in[19], (const float*)d_in[20]);
    k_pnorm<<<(BB * NN) / 256, 256>>>(points);
    if (out_xyz)
        k_newxyz<<<(BB * SS * 3 + 127) / 128, 128>>>(xyz, sidx, out_xyz);
    k_mlp<<<(BB * NN) / 128, 128>>>(points);
    k_dist_mma<<<dim3(SS / 128, BB), 256, DSMEM>>>(points, sidx);
    k_gmax<<<dim3(SS, BB), 128>>>(out_pts);
}

// round 8
// speedup vs baseline: 2.5454x; 2.5454x over previous
#include <cuda_runtime.h>
#include <cfloat>
#include <cstdint>

#define BB 8
#define NN 16384
#define SS 2048
#define DD 64

__device__ float g_pnorm[BB * NN];
__device__ int   g_topk[BB * SS * 32];
__device__ float g_h2[BB * NN * 128];
__device__ float g_w0f[64 * 64], g_w1f[64 * 64], g_w2f[128 * 64];
__device__ float g_b0f[64], g_b1f[64], g_b2f[128];

// ---------------- packed f32x2 helpers (PTX sm_100+ base feature) ----------
__device__ __forceinline__ unsigned long long pk2(float x, float y) {
    unsigned long long r;
    asm("mov.b64 %0, {%1,%2};" : "=l"(r) : "f"(x), "f"(y));
    return r;
}
__device__ __forceinline__ void upk2(float& x, float& y, unsigned long long v) {
    asm("mov.b64 {%0,%1}, %2;" : "=f"(x), "=f"(y) : "l"(v));
}
__device__ __forceinline__ void fmax2(unsigned long long& a, unsigned long long b,
                                      unsigned long long c) {
    asm("fma.rn.f32x2 %0, %1, %2, %0;" : "+l"(a) : "l"(b), "l"(c));
}
__device__ __forceinline__ unsigned long long addx2(unsigned long long a,
                                                    unsigned long long b) {
    unsigned long long r;
    asm("add.rn.f32x2 %0, %1, %2;" : "=l"(r) : "l"(a), "l"(b));
    return r;
}

#define DOT4STEP(wv, h0, h1, h2v, h3, A, Bc) \
    A  = fmaf((h0), (wv).x, A);  Bc = fmaf((h1), (wv).y, Bc); \
    A  = fmaf((h2v), (wv).z, A); Bc = fmaf((h3), (wv).w, Bc);

// ---------------- weight/BN folding ----------------
__global__ void k_prep(const float* __restrict__ w0, const float* __restrict__ b0,
                       const float* __restrict__ gg0, const float* __restrict__ be0,
                       const float* __restrict__ m0, const float* __restrict__ v0,
                       const float* __restrict__ w1, const float* __restrict__ b1,
                       const float* __restrict__ gg1, const float* __restrict__ be1,
                       const float* __restrict__ m1, const float* __restrict__ v1,
                       const float* __restrict__ w2, const float* __restrict__ b2,
                       const float* __restrict__ gg2, const float* __restrict__ be2,
                       const float* __restrict__ m2, const float* __restrict__ v2) {
    int o = threadIdx.x;
    if (o < 64) {
        float s0 = gg0[o] * rsqrtf(v0[o] + 1e-5f);
        for (int c = 0; c < 64; c++) g_w0f[o * 64 + c] = w0[o * 64 + c] * s0;
        g_b0f[o] = (b0[o] - m0[o]) * s0 + be0[o];
        float s1 = gg1[o] * rsqrtf(v1[o] + 1e-5f);
        for (int c = 0; c < 64; c++) g_w1f[o * 64 + c] = w1[o * 64 + c] * s1;
        g_b1f[o] = (b1[o] - m1[o]) * s1 + be1[o];
    }
    float s2 = gg2[o] * rsqrtf(v2[o] + 1e-5f);
    for (int c = 0; c < 64; c++) g_w2f[o * 64 + c] = w2[o * 64 + c] * s2;
    g_b2f[o] = (b2[o] - m2[o]) * s2 + be2[o];
}

__global__ void k_pnorm(const float* __restrict__ points) {
    int i = blockIdx.x * blockDim.x + threadIdx.x;
    const float4* p = (const float4*)(points + (size_t)i * DD);
    float a0 = 0, a1 = 0, a2 = 0, a3 = 0;
#pragma unroll
    for (int u = 0; u < 16; u++) {
        float4 v = p[u];
        a0 = fmaf(v.x, v.x, a0); a1 = fmaf(v.y, v.y, a1);
        a2 = fmaf(v.z, v.z, a2); a3 = fmaf(v.w, v.w, a3);
    }
    g_pnorm[i] = (a0 + a1) + (a2 + a3);
}

__global__ void k_newxyz(const float* __restrict__ xyz, const int* __restrict__ sidx,
                         float* __restrict__ out) {
    int t = blockIdx.x * blockDim.x + threadIdx.x;
    if (t >= BB * SS * 3) return;
    int c = t % 3, s = (t / 3) % SS, b = t / (3 * SS);
    out[t] = xyz[((size_t)b * NN + sidx[s]) * 3 + c];
}

// ---------------- pointwise 3-layer MLP (unchanged, known-good 322us) ------
__global__ void __launch_bounds__(128, 1) k_mlp(const float* __restrict__ points) {
    __shared__ float sh0[64 * 128];
    const int tid = threadIdx.x;
    const size_t pt = (size_t)blockIdx.x * 128 + tid;
    float4 x[16];
    {
        const float4* xp = (const float4*)(points + pt * DD);
#pragma unroll
        for (int u = 0; u < 16; u++) x[u] = xp[u];
    }
    for (int o4 = 0; o4 < 16; o4++) {
        const float4* wr0 = (const float4*)(g_w0f + (o4 * 4 + 0) * 64);
        const float4* wr1 = (const float4*)(g_w0f + (o4 * 4 + 1) * 64);
        const float4* wr2 = (const float4*)(g_w0f + (o4 * 4 + 2) * 64);
        const float4* wr3 = (const float4*)(g_w0f + (o4 * 4 + 3) * 64);
        float A0 = 0, A1 = 0, A2 = 0, A3 = 0, C0 = 0, C1 = 0, C2 = 0, C3 = 0;
#pragma unroll
        for (int u = 0; u < 16; u++) {
            float h0 = x[u].x, h1 = x[u].y, h2v = x[u].z, h3 = x[u].w;
            float4 w0v = wr0[u]; DOT4STEP(w0v, h0, h1, h2v, h3, A0, C0);
            float4 w1v = wr1[u]; DOT4STEP(w1v, h0, h1, h2v, h3, A1, C1);
            float4 w2v = wr2[u]; DOT4STEP(w2v, h0, h1, h2v, h3, A2, C2);
            float4 w3v = wr3[u]; DOT4STEP(w3v, h0, h1, h2v, h3, A3, C3);
        }
        sh0[(o4 * 4 + 0) * 128 + tid] = fmaxf(A0 + C0 + g_b0f[o4 * 4 + 0], 0.f);
        sh0[(o4 * 4 + 1) * 128 + tid] = fmaxf(A1 + C1 + g_b0f[o4 * 4 + 1], 0.f);
        sh0[(o4 * 4 + 2) * 128 + tid] = fmaxf(A2 + C2 + g_b0f[o4 * 4 + 2], 0.f);
        sh0[(o4 * 4 + 3) * 128 + tid] = fmaxf(A3 + C3 + g_b0f[o4 * 4 + 3], 0.f);
    }
    float h1r[64];
#pragma unroll
    for (int o4 = 0; o4 < 16; o4++) {
        const float4* wr0 = (const float4*)(g_w1f + (o4 * 4 + 0) * 64);
        const float4* wr1 = (const float4*)(g_w1f + (o4 * 4 + 1) * 64);
        const float4* wr2 = (const float4*)(g_w1f + (o4 * 4 + 2) * 64);
        const float4* wr3 = (const float4*)(g_w1f + (o4 * 4 + 3) * 64);
        float A0 = 0, A1 = 0, A2 = 0, A3 = 0, C0 = 0, C1 = 0, C2 = 0, C3 = 0;
#pragma unroll
        for (int u = 0; u < 16; u++) {
            float h0 = sh0[(4 * u + 0) * 128 + tid];
            float h1 = sh0[(4 * u + 1) * 128 + tid];
            float h2v = sh0[(4 * u + 2) * 128 + tid];
            float h3 = sh0[(4 * u + 3) * 128 + tid];
            float4 w0v = wr0[u]; DOT4STEP(w0v, h0, h1, h2v, h3, A0, C0);
            float4 w1v = wr1[u]; DOT4STEP(w1v, h0, h1, h2v, h3, A1, C1);
            float4 w2v = wr2[u]; DOT4STEP(w2v, h0, h1, h2v, h3, A2, C2);
            float4 w3v = wr3[u]; DOT4STEP(w3v, h0, h1, h2v, h3, A3, C3);
        }
        h1r[o4 * 4 + 0] = fmaxf(A0 + C0 + g_b1f[o4 * 4 + 0], 0.f);
        h1r[o4 * 4 + 1] = fmaxf(A1 + C1 + g_b1f[o4 * 4 + 1], 0.f);
        h1r[o4 * 4 + 2] = fmaxf(A2 + C2 + g_b1f[o4 * 4 + 2], 0.f);
        h1r[o4 * 4 + 3] = fmaxf(A3 + C3 + g_b1f[o4 * 4 + 3], 0.f);
    }
    float* stg = sh0;
    const size_t obase = (size_t)blockIdx.x * 128 * 128;
    for (int ch = 0; ch < 4; ch++) {
        __syncthreads();
        for (int o4 = 0; o4 < 8; o4++) {
            const int ob = ch * 32 + o4 * 4;
            const float4* wr0 = (const float4*)(g_w2f + (ob + 0) * 64);
            const float4* wr1 = (const float4*)(g_w2f + (ob + 1) * 64);
            const float4* wr2 = (const float4*)(g_w2f + (ob + 2) * 64);
            const float4* wr3 = (const float4*)(g_w2f + (ob + 3) * 64);
            float A0 = 0, A1 = 0, A2 = 0, A3 = 0, C0 = 0, C1 = 0, C2 = 0, C3 = 0;
#pragma unroll
            for (int u = 0; u < 16; u++) {
                float h0 = h1r[4 * u + 0], h1 = h1r[4 * u + 1];
                float h2v = h1r[4 * u + 2], h3 = h1r[4 * u + 3];
                float4 w0v = wr0[u]; DOT4STEP(w0v, h0, h1, h2v, h3, A0, C0);
                float4 w1v = wr1[u]; DOT4STEP(w1v, h0, h1, h2v, h3, A1, C1);
                float4 w2v = wr2[u]; DOT4STEP(w2v, h0, h1, h2v, h3, A2, C2);
                float4 w3v = wr3[u]; DOT4STEP(w3v, h0, h1, h2v, h3, A3, C3);
            }
            stg[(o4 * 4 + 0) * 129 + tid] = fmaxf(A0 + C0 + g_b2f[ob + 0], 0.f);
            stg[(o4 * 4 + 1) * 129 + tid] = fmaxf(A1 + C1 + g_b2f[ob + 1], 0.f);
            stg[(o4 * 4 + 2) * 129 + tid] = fmaxf(A2 + C2 + g_b2f[ob + 2], 0.f);
            stg[(o4 * 4 + 3) * 129 + tid] = fmaxf(A3 + C3 + g_b2f[ob + 3], 0.f);
        }
        __syncthreads();
        const int lane = tid & 31, grp = tid >> 5;
#pragma unroll 4
        for (int rr = grp; rr < 128; rr += 4) {
            g_h2[obase + (size_t)rr * 128 + ch * 32 + lane] = stg[lane * 129 + rr];
        }
    }
}

// ============================================================================
// k_dist2: f32x2 packed distance GEMV + running top-32
//   256 threads; pair (tid, tid+128) serves sample (s0 + tid&127):
//   half 0 handles even tiles, half 1 odd tiles; exact merge at the end.
// ============================================================================
__global__ void __launch_bounds__(256, 1) k_dist2(const float* __restrict__ points,
                                                  const int* __restrict__ sidx) {
    extern __shared__ float dsm[];
    float* sP  = dsm;                 // [2][128][64] = 16384 floats
    float* sPn = dsm + 16384;         // [2][128]
    float* stv = sPn + 256;           // [256][33]
    int*   sti = (int*)(stv + 256 * 33);

    const int tid = threadIdx.x;
    const int half = tid >> 7;        // 0: even tiles, 1: odd tiles
    const int l128 = tid & 127;
    const int b = blockIdx.y;
    const int s0 = blockIdx.x * 128;

    // load query row, negate-and-scale (q2 = -2q), pack into 32 u64 regs
    unsigned long long q2[32];
    {
        const int qi = __ldg(sidx + s0 + l128);
        const float4* qp = (const float4*)(points + ((size_t)b * NN + qi) * DD);
#pragma unroll
        for (int u = 0; u < 16; u++) {
            float4 v = qp[u];
            q2[2 * u]     = pk2(-2.f * v.x, -2.f * v.y);
            q2[2 * u + 1] = pk2(-2.f * v.z, -2.f * v.w);
        }
    }

#pragma unroll
    for (int j = 0; j < 32; j++) stv[tid * 33 + j] = FLT_MAX;
    float thr = FLT_MAX;
    int slot = 0;

    const float4* Pb = (const float4*)(points + (size_t)b * NN * DD);
    const float*  Pn = g_pnorm + b * NN;
    const float*  tp = sP + half * 8192;
    const float*  pn = sPn + half * 128;

    for (int r = 0; r < 64; r++) {
        __syncthreads();
        {   // load tiles 2r, 2r+1 (4096 float4, 16 per thread) + 256 pnorms
            float4* dst = (float4*)sP;
            const float4* src = Pb + (size_t)r * 4096;
#pragma unroll
            for (int i = 0; i < 16; i++) dst[tid + i * 256] = src[tid + i * 256];
            sPn[tid] = Pn[r * 256 + tid];
        }
        __syncthreads();

        const int ibase = (2 * r + half) * 128;
#pragma unroll 2
        for (int p = 0; p < 128; p++) {
            const ulonglong2* pv = (const ulonglong2*)(tp + p * 64);
            unsigned long long a0 = pk2(pn[p], 0.f);
            unsigned long long a1 = 0ull;
#pragma unroll
            for (int i = 0; i < 16; i++) {     // 16 ulonglong2 = full 64 dims
                ulonglong2 w = pv[i];
                fmax2(a0, q2[2 * i], w.x);
                fmax2(a1, q2[2 * i + 1], w.y);
            }
            a0 = addx2(a0, a1);
            float lo, hi;
            upk2(lo, hi, a0);
            float sc = lo + hi;
            if (sc < thr) {
                stv[tid * 33 + slot] = sc;
                sti[tid * 33 + slot] = ibase + p;
                float m = -FLT_MAX; int ms = 0;
#pragma unroll
                for (int j = 0; j < 32; j++) {
                    float vv = stv[tid * 33 + j];
                    if (vv > m) { m = vv; ms = j; }
                }
                thr = m; slot = ms;
            }
        }
    }

    __syncthreads();
    // exact merge of the two 32-lists per sample (value asc, ties by index)
    if (tid < 128) {
        float* v0 = stv + tid * 33;        int* i0 = sti + tid * 33;
        float* v1 = stv + (tid + 128) * 33; int* i1 = sti + (tid + 128) * 33;
        int* op = g_topk + ((size_t)b * SS + s0 + tid) * 32;
        for (int k = 0; k < 32; k++) {
            float m = FLT_MAX; int mi = 0x7fffffff, msel = 0, sel1 = 0;
#pragma unroll
            for (int j = 0; j < 32; j++) {
                float v = v0[j];
                if (v < m || (v == m && i0[j] < mi)) { m = v; mi = i0[j]; msel = j; sel1 = 0; }
            }
#pragma unroll
            for (int j = 0; j < 32; j++) {
                float v = v1[j];
                if (v < m || (v == m && i1[j] < mi)) { m = v; mi = i1[j]; msel = j; sel1 = 1; }
            }
            op[k] = mi;
            if (sel1) v1[msel] = FLT_MAX; else v0[msel] = FLT_MAX;
        }
    }
}

// ---------------- gather + channel max over the 32 neighbors ----------------
__global__ void k_gmax(float* __restrict__ out) {
    const int b = blockIdx.y, s = blockIdx.x, c = threadIdx.x;
    __shared__ int si[32];
    if (threadIdx.x < 32) si[threadIdx.x] = g_topk[((size_t)b * SS + s) * 32 + threadIdx.x];
    __syncthreads();
    const float* hb = g_h2 + (size_t)b * NN * 128;
    float m = -FLT_MAX;
#pragma unroll 8
    for (int j = 0; j < 32; j++) m = fmaxf(m, hb[(size_t)si[j] * 128 + c]);
    out[((size_t)b * SS + s) * 128 + c] = m;
}

// ---------------- launch ----------------
extern "C" void kernel_launch(void* const* d_in, const int* in_sizes, int n_in,
                              void* d_out, int out_size) {
    const float* xyz    = (const float*)d_in[0];
    const float* points = (const float*)d_in[1];
    const int*   sidx   = (const int*)d_in[2];

    float* out = (float*)d_out;
    float* out_xyz = nullptr;
    float* out_pts = out;
    if (out_size == BB * SS * 3 + BB * SS * 128) {
        out_xyz = out;
        out_pts = out + BB * SS * 3;
    }

    const int dist_smem = (16384 + 256 + 256 * 33 * 2) * 4;  // 134144 B
    cudaFuncSetAttribute(k_dist2, cudaFuncAttributeMaxDynamicSharedMemorySize, dist_smem);

    k_prep<<<1, 128>>>((const float*)d_in[3], (const float*)d_in[4], (const float*)d_in[5],
                       (const float*)d_in[6], (const float*)d_in[7], (const float*)d_in[8],
                       (const float*)d_in[9], (const float*)d_in[10], (const float*)d_in[11],
                       (const float*)d_in[12], (const float*)d_in[13], (const float*)d_in[14],
                       (const float*)d_in[15], (const float*)d_in[16], (const float*)d_in[17],
                       (const float*)d_in[18], (const float*)d_in[19], (const float*)d_in[20]);
    k_pnorm<<<(BB * NN) / 256, 256>>>(points);
    if (out_xyz)
        k_newxyz<<<(BB * SS * 3 + 127) / 128, 128>>>(xyz, sidx, out_xyz);
    k_mlp<<<(BB * NN) / 128, 128>>>(points);
    k_dist2<<<dim3(SS / 128, BB), 256, dist_smem>>>(points, sidx);
    k_gmax<<<dim3(SS, BB), 128>>>(out_pts);
}

// round 9
// speedup vs baseline: 2.6429x; 1.0383x over previous
#include <cuda_runtime.h>
#include <cfloat>
#include <cstdint>

#define BB 8
#define NN 16384
#define SS 2048
#define DD 64

__device__ float g_pnorm[BB * NN];
__device__ int   g_topk[BB * SS * 32];
__device__ float g_h2[BB * NN * 128];
__device__ float g_w0f[64 * 64], g_w1f[64 * 64], g_w2f[128 * 64];
__device__ float g_b0f[64], g_b1f[64], g_b2f[128];

// ---------------- packed f32x2 + cp.async helpers ----------------
__device__ __forceinline__ uint32_t smem_u32(const void* p) {
    uint32_t a;
    asm("{ .reg .u64 t; cvta.to.shared.u64 t, %1; cvt.u32.u64 %0, t; }" : "=r"(a) : "l"(p));
    return a;
}
__device__ __forceinline__ unsigned long long pk2(float x, float y) {
    unsigned long long r;
    asm("mov.b64 %0, {%1,%2};" : "=l"(r) : "f"(x), "f"(y));
    return r;
}
__device__ __forceinline__ void upk2(float& x, float& y, unsigned long long v) {
    asm("mov.b64 {%0,%1}, %2;" : "=f"(x), "=f"(y) : "l"(v));
}
__device__ __forceinline__ void fmax2(unsigned long long& a, unsigned long long b,
                                      unsigned long long c) {
    asm("fma.rn.f32x2 %0, %1, %2, %0;" : "+l"(a) : "l"(b), "l"(c));
}
__device__ __forceinline__ unsigned long long addx2(unsigned long long a,
                                                    unsigned long long b) {
    unsigned long long r;
    asm("add.rn.f32x2 %0, %1, %2;" : "=l"(r) : "l"(a), "l"(b));
    return r;
}
#define CPA16(dst, src) \
    asm volatile("cp.async.cg.shared.global [%0], [%1], 16;" :: "r"(dst), "l"(src))
#define CPA4(dst, src) \
    asm volatile("cp.async.ca.shared.global [%0], [%1], 4;" :: "r"(dst), "l"(src))
#define CPA_COMMIT() asm volatile("cp.async.commit_group;" ::: "memory")
#define CPA_WAIT1()  asm volatile("cp.async.wait_group 1;" ::: "memory")

#define DOT4STEP(wv, h0, h1, h2v, h3, A, Bc) \
    A  = fmaf((h0), (wv).x, A);  Bc = fmaf((h1), (wv).y, Bc); \
    A  = fmaf((h2v), (wv).z, A); Bc = fmaf((h3), (wv).w, Bc);

// ---------------- weight/BN folding ----------------
__global__ void k_prep(const float* __restrict__ w0, const float* __restrict__ b0,
                       const float* __restrict__ gg0, const float* __restrict__ be0,
                       const float* __restrict__ m0, const float* __restrict__ v0,
                       const float* __restrict__ w1, const float* __restrict__ b1,
                       const float* __restrict__ gg1, const float* __restrict__ be1,
                       const float* __restrict__ m1, const float* __restrict__ v1,
                       const float* __restrict__ w2, const float* __restrict__ b2,
                       const float* __restrict__ gg2, const float* __restrict__ be2,
                       const float* __restrict__ m2, const float* __restrict__ v2) {
    int o = threadIdx.x;
    if (o < 64) {
        float s0 = gg0[o] * rsqrtf(v0[o] + 1e-5f);
        for (int c = 0; c < 64; c++) g_w0f[o * 64 + c] = w0[o * 64 + c] * s0;
        g_b0f[o] = (b0[o] - m0[o]) * s0 + be0[o];
        float s1 = gg1[o] * rsqrtf(v1[o] + 1e-5f);
        for (int c = 0; c < 64; c++) g_w1f[o * 64 + c] = w1[o * 64 + c] * s1;
        g_b1f[o] = (b1[o] - m1[o]) * s1 + be1[o];
    }
    float s2 = gg2[o] * rsqrtf(v2[o] + 1e-5f);
    for (int c = 0; c < 64; c++) g_w2f[o * 64 + c] = w2[o * 64 + c] * s2;
    g_b2f[o] = (b2[o] - m2[o]) * s2 + be2[o];
}

__global__ void k_pnorm(const float* __restrict__ points) {
    int i = blockIdx.x * blockDim.x + threadIdx.x;
    const float4* p = (const float4*)(points + (size_t)i * DD);
    float a0 = 0, a1 = 0, a2 = 0, a3 = 0;
#pragma unroll
    for (int u = 0; u < 16; u++) {
        float4 v = p[u];
        a0 = fmaf(v.x, v.x, a0); a1 = fmaf(v.y, v.y, a1);
        a2 = fmaf(v.z, v.z, a2); a3 = fmaf(v.w, v.w, a3);
    }
    g_pnorm[i] = (a0 + a1) + (a2 + a3);
}

__global__ void k_newxyz(const float* __restrict__ xyz, const int* __restrict__ sidx,
                         float* __restrict__ out) {
    int t = blockIdx.x * blockDim.x + threadIdx.x;
    if (t >= BB * SS * 3) return;
    int c = t % 3, s = (t / 3) % SS, b = t / (3 * SS);
    out[t] = xyz[((size_t)b * NN + sidx[s]) * 3 + c];
}

// ---------------- pointwise 3-layer MLP (unchanged, known-good) ------------
__global__ void __launch_bounds__(128, 1) k_mlp(const float* __restrict__ points) {
    __shared__ float sh0[64 * 128];
    const int tid = threadIdx.x;
    const size_t pt = (size_t)blockIdx.x * 128 + tid;
    float4 x[16];
    {
        const float4* xp = (const float4*)(points + pt * DD);
#pragma unroll
        for (int u = 0; u < 16; u++) x[u] = xp[u];
    }
    for (int o4 = 0; o4 < 16; o4++) {
        const float4* wr0 = (const float4*)(g_w0f + (o4 * 4 + 0) * 64);
        const float4* wr1 = (const float4*)(g_w0f + (o4 * 4 + 1) * 64);
        const float4* wr2 = (const float4*)(g_w0f + (o4 * 4 + 2) * 64);
        const float4* wr3 = (const float4*)(g_w0f + (o4 * 4 + 3) * 64);
        float A0 = 0, A1 = 0, A2 = 0, A3 = 0, C0 = 0, C1 = 0, C2 = 0, C3 = 0;
#pragma unroll
        for (int u = 0; u < 16; u++) {
            float h0 = x[u].x, h1 = x[u].y, h2v = x[u].z, h3 = x[u].w;
            float4 w0v = wr0[u]; DOT4STEP(w0v, h0, h1, h2v, h3, A0, C0);
            float4 w1v = wr1[u]; DOT4STEP(w1v, h0, h1, h2v, h3, A1, C1);
            float4 w2v = wr2[u]; DOT4STEP(w2v, h0, h1, h2v, h3, A2, C2);
            float4 w3v = wr3[u]; DOT4STEP(w3v, h0, h1, h2v, h3, A3, C3);
        }
        sh0[(o4 * 4 + 0) * 128 + tid] = fmaxf(A0 + C0 + g_b0f[o4 * 4 + 0], 0.f);
        sh0[(o4 * 4 + 1) * 128 + tid] = fmaxf(A1 + C1 + g_b0f[o4 * 4 + 1], 0.f);
        sh0[(o4 * 4 + 2) * 128 + tid] = fmaxf(A2 + C2 + g_b0f[o4 * 4 + 2], 0.f);
        sh0[(o4 * 4 + 3) * 128 + tid] = fmaxf(A3 + C3 + g_b0f[o4 * 4 + 3], 0.f);
    }
    float h1r[64];
#pragma unroll
    for (int o4 = 0; o4 < 16; o4++) {
        const float4* wr0 = (const float4*)(g_w1f + (o4 * 4 + 0) * 64);
        const float4* wr1 = (const float4*)(g_w1f + (o4 * 4 + 1) * 64);
        const float4* wr2 = (const float4*)(g_w1f + (o4 * 4 + 2) * 64);
        const float4* wr3 = (const float4*)(g_w1f + (o4 * 4 + 3) * 64);
        float A0 = 0, A1 = 0, A2 = 0, A3 = 0, C0 = 0, C1 = 0, C2 = 0, C3 = 0;
#pragma unroll
        for (int u = 0; u < 16; u++) {
            float h0 = sh0[(4 * u + 0) * 128 + tid];
            float h1 = sh0[(4 * u + 1) * 128 + tid];
            float h2v = sh0[(4 * u + 2) * 128 + tid];
            float h3 = sh0[(4 * u + 3) * 128 + tid];
            float4 w0v = wr0[u]; DOT4STEP(w0v, h0, h1, h2v, h3, A0, C0);
            float4 w1v = wr1[u]; DOT4STEP(w1v, h0, h1, h2v, h3, A1, C1);
            float4 w2v = wr2[u]; DOT4STEP(w2v, h0, h1, h2v, h3, A2, C2);
            float4 w3v = wr3[u]; DOT4STEP(w3v, h0, h1, h2v, h3, A3, C3);
        }
        h1r[o4 * 4 + 0] = fmaxf(A0 + C0 + g_b1f[o4 * 4 + 0], 0.f);
        h1r[o4 * 4 + 1] = fmaxf(A1 + C1 + g_b1f[o4 * 4 + 1], 0.f);
        h1r[o4 * 4 + 2] = fmaxf(A2 + C2 + g_b1f[o4 * 4 + 2], 0.f);
        h1r[o4 * 4 + 3] = fmaxf(A3 + C3 + g_b1f[o4 * 4 + 3], 0.f);
    }
    float* stg = sh0;
    const size_t obase = (size_t)blockIdx.x * 128 * 128;
    for (int ch = 0; ch < 4; ch++) {
        __syncthreads();
        for (int o4 = 0; o4 < 8; o4++) {
            const int ob = ch * 32 + o4 * 4;
            const float4* wr0 = (const float4*)(g_w2f + (ob + 0) * 64);
            const float4* wr1 = (const float4*)(g_w2f + (ob + 1) * 64);
            const float4* wr2 = (const float4*)(g_w2f + (ob + 2) * 64);
            const float4* wr3 = (const float4*)(g_w2f + (ob + 3) * 64);
            float A0 = 0, A1 = 0, A2 = 0, A3 = 0, C0 = 0, C1 = 0, C2 = 0, C3 = 0;
#pragma unroll
            for (int u = 0; u < 16; u++) {
                float h0 = h1r[4 * u + 0], h1 = h1r[4 * u + 1];
                float h2v = h1r[4 * u + 2], h3 = h1r[4 * u + 3];
                float4 w0v = wr0[u]; DOT4STEP(w0v, h0, h1, h2v, h3, A0, C0);
                float4 w1v = wr1[u]; DOT4STEP(w1v, h0, h1, h2v, h3, A1, C1);
                float4 w2v = wr2[u]; DOT4STEP(w2v, h0, h1, h2v, h3, A2, C2);
                float4 w3v = wr3[u]; DOT4STEP(w3v, h0, h1, h2v, h3, A3, C3);
            }
            stg[(o4 * 4 + 0) * 129 + tid] = fmaxf(A0 + C0 + g_b2f[ob + 0], 0.f);
            stg[(o4 * 4 + 1) * 129 + tid] = fmaxf(A1 + C1 + g_b2f[ob + 1], 0.f);
            stg[(o4 * 4 + 2) * 129 + tid] = fmaxf(A2 + C2 + g_b2f[ob + 2], 0.f);
            stg[(o4 * 4 + 3) * 129 + tid] = fmaxf(A3 + C3 + g_b2f[ob + 3], 0.f);
        }
        __syncthreads();
        const int lane = tid & 31, grp = tid >> 5;
#pragma unroll 4
        for (int rr = grp; rr < 128; rr += 4) {
            g_h2[obase + (size_t)rr * 128 + ch * 32 + lane] = stg[lane * 129 + rr];
        }
    }
}

// ============================================================================
// k_dist3: 512 threads, thread-quad per sample, cp.async double-buffered tiles
// ============================================================================
// smem float offsets
#define DS_SP  0u       // [2][128*64]
#define DS_PN  16384u   // [2][128]
#define DS_TV  16640u   // [512][33]
#define DS_TI  33536u   // [512][33] (ints)
#define DS_TOTB (50432 * 4)

__global__ void __launch_bounds__(512, 1) k_dist3(const float* __restrict__ points,
                                                  const int* __restrict__ sidx) {
    extern __shared__ float dsm[];
    const uint32_t sb = smem_u32(dsm);
    const int tid = threadIdx.x;
    const int qh = tid >> 7, l128 = tid & 127;
    const int b = blockIdx.y, s0 = blockIdx.x * 128;

    float* stv = dsm + DS_TV;
    int*   sti = (int*)(dsm + DS_TI);

    // query row scaled by 2, packed (k,k+1) pairs
    unsigned long long q2[32];
    {
        const int qi = __ldg(sidx + s0 + l128);
        const float4* qp = (const float4*)(points + ((size_t)b * NN + qi) * DD);
#pragma unroll
        for (int u = 0; u < 16; u++) {
            float4 v = qp[u];
            q2[2 * u]     = pk2(2.f * v.x, 2.f * v.y);
            q2[2 * u + 1] = pk2(2.f * v.z, 2.f * v.w);
        }
    }
#pragma unroll
    for (int j = 0; j < 32; j++) stv[tid * 33 + j] = FLT_MAX;
    float thr = FLT_MAX;
    int slot = 0;

    const float4* Pb = (const float4*)(points + (size_t)b * NN * DD);
    const float*  Pn = g_pnorm + b * NN;

    // prologue: tile 0 -> buf 0
    {
        uint32_t d = sb + DS_SP * 4 + tid * 16;
        const float4* s = Pb + tid;
#pragma unroll
        for (int i = 0; i < 4; i++) CPA16(d + i * 8192u, s + i * 512);
        if (tid < 128) CPA4(sb + (DS_PN + tid) * 4, Pn + tid);
    }
    CPA_COMMIT();

    for (int t = 0; t < 128; t++) {
        const int cur = t & 1;
        if (t < 127) {
            const int nxt = cur ^ 1;
            uint32_t d = sb + (DS_SP + nxt * 8192u) * 4 + tid * 16;
            const float4* s = Pb + (size_t)(t + 1) * 2048 + tid;
#pragma unroll
            for (int i = 0; i < 4; i++) CPA16(d + i * 8192u, s + i * 512);
            if (tid < 128) CPA4(sb + (DS_PN + nxt * 128u + tid) * 4, Pn + (t + 1) * 128 + tid);
        }
        CPA_COMMIT();
        CPA_WAIT1();
        __syncthreads();

        const float* tp = dsm + DS_SP + cur * 8192 + qh * 32 * 64;
        const float* pn = dsm + DS_PN + cur * 128 + qh * 32;
        const int ibase = t * 128 + qh * 32;
#pragma unroll 2
        for (int p = 0; p < 32; p++) {
            const ulonglong2* pv = (const ulonglong2*)(tp + p * 64);
            unsigned long long a0 = 0ull, a1 = 0ull;
#pragma unroll
            for (int i = 0; i < 16; i++) {
                ulonglong2 w = pv[i];
                fmax2(a0, q2[2 * i], w.x);
                fmax2(a1, q2[2 * i + 1], w.y);
            }
            a0 = addx2(a0, a1);
            float lo, hi;
            upk2(lo, hi, a0);
            float sc = pn[p] - (lo + hi);   // dot first, pn subtracted once (R1 numerics)
            if (sc < thr) {
                stv[tid * 33 + slot] = sc;
                sti[tid * 33 + slot] = ibase + p;
                float m = -FLT_MAX; int ms = 0;
#pragma unroll
                for (int j = 0; j < 32; j++) {
                    float vv = stv[tid * 33 + j];
                    if (vv > m) { m = vv; ms = j; }
                }
                thr = m; slot = ms;
            }
        }
        __syncthreads();   // all reads of buf[cur] done before it is refilled
    }

    // exact 4-way merge per sample by (value, index)
    if (tid < 128) {
        int* op = g_topk + ((size_t)b * SS + s0 + tid) * 32;
        for (int k = 0; k < 32; k++) {
            float m = FLT_MAX; int mi = 0x7fffffff, sel = 0;
#pragma unroll
            for (int h = 0; h < 4; h++) {
                const int base = (tid + 128 * h) * 33;
                for (int j = 0; j < 32; j++) {
                    float v = stv[base + j];
                    int   ii = sti[base + j];
                    if (v < m || (v == m && ii < mi)) { m = v; mi = ii; sel = base + j; }
                }
            }
            op[k] = mi;
            stv[sel] = FLT_MAX;
        }
    }
}

// ---------------- gather + channel max over the 32 neighbors ----------------
__global__ void k_gmax(float* __restrict__ out) {
    const int b = blockIdx.y, s = blockIdx.x, c = threadIdx.x;
    __shared__ int si[32];
    if (threadIdx.x < 32) si[threadIdx.x] = g_topk[((size_t)b * SS + s) * 32 + threadIdx.x];
    __syncthreads();
    const float* hb = g_h2 + (size_t)b * NN * 128;
    float m = -FLT_MAX;
#pragma unroll 8
    for (int j = 0; j < 32; j++) m = fmaxf(m, hb[(size_t)si[j] * 128 + c]);
    out[((size_t)b * SS + s) * 128 + c] = m;
}

// ---------------- launch (k_dist3 moved before k_mlp for ncu capture) -------
extern "C" void kernel_launch(void* const* d_in, const int* in_sizes, int n_in,
                              void* d_out, int out_size) {
    const float* xyz    = (const float*)d_in[0];
    const float* points = (const float*)d_in[1];
    const int*   sidx   = (const int*)d_in[2];

    float* out = (float*)d_out;
    float* out_xyz = nullptr;
    float* out_pts = out;
    if (out_size == BB * SS * 3 + BB * SS * 128) {
        out_xyz = out;
        out_pts = out + BB * SS * 3;
    }

    cudaFuncSetAttribute(k_dist3, cudaFuncAttributeMaxDynamicSharedMemorySize, DS_TOTB);

    k_prep<<<1, 128>>>((const float*)d_in[3], (const float*)d_in[4], (const float*)d_in[5],
                       (const float*)d_in[6], (const float*)d_in[7], (const float*)d_in[8],
                       (const float*)d_in[9], (const float*)d_in[10], (const float*)d_in[11],
                       (const float*)d_in[12], (const float*)d_in[13], (const float*)d_in[14],
                       (const float*)d_in[15], (const float*)d_in[16], (const float*)d_in[17],
                       (const float*)d_in[18], (const float*)d_in[19], (const float*)d_in[20]);
    k_pnorm<<<(BB * NN) / 256, 256>>>(points);
    if (out_xyz)
        k_newxyz<<<(BB * SS * 3 + 127) / 128, 128>>>(xyz, sidx, out_xyz);
    k_dist3<<<dim3(SS / 128, BB), 512, DS_TOTB>>>(points, sidx);
    k_mlp<<<(BB * NN) / 128, 128>>>(points);
    k_gmax<<<dim3(SS, BB), 128>>>(out_pts);
}